// round 9
// baseline (speedup 1.0000x reference)
#include <cuda_runtime.h>

// Cumulative accumulators: [0]=sum(d^2), [1..5]=T0..T4, [6..10]=C0..C4
__device__ double g_acc[11];
__device__ unsigned int g_ticket;

#define BLOCKS_PER_SM 5
#define GRID (148 * BLOCKS_PER_SM)   // 740, one full wave
#define TPB  256
#define BMAG 1024.0f                 // count-fusion magnitude (power of 2)

// w_k = (t >= q_k) AND (t <= q5), as 1.0f/0.0f via single FSET.AND each.
__device__ __forceinline__ void bin_weights(float t, float q0, float q1, float q2,
                                            float q3, float q4, float q5,
                                            float& w0, float& w1, float& w2,
                                            float& w3, float& w4)
{
    asm("{\n\t"
        ".reg .pred h;\n\t"
        "setp.le.f32 h, %5, %11;\n\t"
        "set.ge.and.f32.f32 %0, %5, %6, h;\n\t"
        "set.ge.and.f32.f32 %1, %5, %7, h;\n\t"
        "set.ge.and.f32.f32 %2, %5, %8, h;\n\t"
        "set.ge.and.f32.f32 %3, %5, %9, h;\n\t"
        "set.ge.and.f32.f32 %4, %5, %10, h;\n\t"
        "}"
        : "=f"(w0), "=f"(w1), "=f"(w2), "=f"(w3), "=f"(w4)
        : "f"(t), "f"(q0), "f"(q1), "f"(q2), "f"(q3), "f"(q4), "f"(q5));
}

__global__ void __launch_bounds__(TPB, BLOCKS_PER_SM)
fused_loss_kernel(const float* __restrict__ y_pred,
                  const float* __restrict__ y_true,
                  const float* __restrict__ quants,
                  float* __restrict__ out, int n)
{
    const float q0 = quants[0], q1 = quants[1], q2 = quants[2];
    const float q3 = quants[3], q4 = quants[4], q5 = quants[5];

    float mse = 0.0f;
    float U0 = 0, U1 = 0, U2 = 0, U3 = 0, U4 = 0;   // U_k = T_k + BMAG*C_k

    const int stride = GRID * TPB;
    const int tid    = blockIdx.x * TPB + threadIdx.x;
    const int n4     = n >> 2;
    const float4* __restrict__ p4 = (const float4*)y_pred;
    const float4* __restrict__ t4 = (const float4*)y_true;

#define PR(p_, t_)                                          \
    do {                                                    \
        float t = (t_);                                     \
        float d = (p_)-t;                                   \
        mse = fmaf(d, d, mse);                              \
        float e = d + BMAG;                                 \
        float w0, w1, w2, w3, w4;                           \
        bin_weights(t, q0, q1, q2, q3, q4, q5,              \
                    w0, w1, w2, w3, w4);                    \
        U0 = fmaf(w0, e, U0);                               \
        U1 = fmaf(w1, e, U1);                               \
        U2 = fmaf(w2, e, U2);                               \
        U3 = fmaf(w3, e, U3);                               \
        U4 = fmaf(w4, e, U4);                               \
    } while (0)

    // ---- 2-deep register-pipelined main loop: next batch's loads are always
    // in flight while the current batch computes (continuous MLP) ----
    {
        int i = tid;
        float4 pc = {0, 0, 0, 0}, tc = {0, 0, 0, 0};
        float4 pn = {0, 0, 0, 0}, tn = {0, 0, 0, 0};
        bool cur = (i < n4);
        if (cur) { pc = p4[i]; tc = t4[i]; }
        int j = i + stride;
        while (cur) {
            bool nxt = (j < n4);
            if (nxt) { pn = p4[j]; tn = t4[j]; }
            PR(pc.x, tc.x); PR(pc.y, tc.y); PR(pc.z, tc.z); PR(pc.w, tc.w);
            pc = pn; tc = tn;
            j += stride;
            cur = nxt;
        }
    }
    // scalar tail (n not divisible by 4)
    for (int j = (n4 << 2) + tid; j < n; j += stride) {
        float p = y_pred[j];
        float t = y_true[j];
        PR(p, t);
    }
#undef PR

    // per-thread recovery: C = rint(U/B), T = U - B*C (both exact)
    float v[11];
    v[0] = mse;
    {
        float Us[5] = {U0, U1, U2, U3, U4};
#pragma unroll
        for (int k = 0; k < 5; k++) {
            float c = rintf(Us[k] * (1.0f / BMAG));
            v[1 + k] = fmaf(-BMAG, c, Us[k]);   // T_k
            v[6 + k] = c;                       // C_k
        }
    }

    // ---- block reduction of 11 partials ----
#pragma unroll
    for (int k = 0; k < 11; k++) {
#pragma unroll
        for (int off = 16; off > 0; off >>= 1)
            v[k] += __shfl_down_sync(0xFFFFFFFFu, v[k], off);
    }

    __shared__ float shred[TPB / 32][11];
    const int wid = threadIdx.x >> 5;
    const int lid = threadIdx.x & 31;
    if (lid == 0) {
#pragma unroll
        for (int k = 0; k < 11; k++) shred[wid][k] = v[k];
    }
    __syncthreads();

    if (threadIdx.x < 11) {
        float acc = 0.0f;
#pragma unroll
        for (int w = 0; w < TPB / 32; w++) acc += shred[w][threadIdx.x];
        atomicAdd(&g_acc[threadIdx.x], (double)acc);
    }

    // ---- last block finalizes and resets (graph-replay safe) ----
    __syncthreads();
    if (threadIdx.x == 0) {
        __threadfence();
        unsigned int ticket = atomicAdd(&g_ticket, 1u);
        if (ticket == GRID - 1) {
            double A[11];
#pragma unroll
            for (int k = 0; k < 11; k++) A[k] = atomicAdd(&g_acc[k], 0.0);

            double mse_d = A[0] / (double)n;
            double m = 0.0;
#pragma unroll
            for (int j = 0; j < 5; j++) {
                double s = A[1 + j] - ((j < 4) ? A[2 + j] : 0.0);   // T_j - T_{j+1}
                double c = A[6 + j] - ((j < 4) ? A[7 + j] : 0.0);   // C_j - C_{j+1}
                double b = s / fmax(c, 1.0);
                double b2 = (c > 0.0) ? b * b : 0.0;
                m = fmax(m, b2);
            }
            m = fmax(m, 0.0);
            out[0] = (float)(mse_d + 5.0 * m);

#pragma unroll
            for (int k = 0; k < 11; k++) g_acc[k] = 0.0;
            __threadfence();
            g_ticket = 0u;
        }
    }
}

extern "C" void kernel_launch(void* const* d_in, const int* in_sizes, int n_in,
                              void* d_out, int out_size) {
    const float* y_pred = (const float*)d_in[0];
    const float* y_true = (const float*)d_in[1];
    const float* quants = (const float*)d_in[2];
    float* out = (float*)d_out;
    const int n = in_sizes[0];

    fused_loss_kernel<<<GRID, TPB>>>(y_pred, y_true, quants, out, n);
}